// round 15
// baseline (speedup 1.0000x reference)
#include <cuda_runtime.h>

#define H 128
#define MAXP 25000
#define STRIDE 64        // total ELL row stride: 2 segments x 32 slots
#define SEG 32           // slots per segment (Poisson(12) per segment => safe)

typedef unsigned long long ull;

// Device-global scratch (allocations forbidden). Zero at load; cnt arrays are
// reset by k_gather after use so every graph replay starts clean.
__device__ __align__(256) float g_agg[MAXP * H];
__device__ __align__(256) float g_sagg[MAXP * H];
__device__ int g_pcnt[MAXP * 2], g_scnt[MAXP * 2];   // 2 sub-counters per row
__device__ int g_pesrc[MAXP * STRIDE], g_sesrc[MAXP * STRIDE];
__device__ __align__(16) ull g_wp[64 * H];  // g_wp[kk2*H + c] = (W[c][2kk2], W[c][2kk2+1])

__device__ __forceinline__ ull fma2(ull a, ull b, ull c) {
    ull d;
    asm("fma.rn.f32x2 %0, %1, %2, %3;" : "=l"(d) : "l"(a), "l"(b), "l"(c));
    return d;
}
__device__ __forceinline__ ull packf2(float lo, float hi) {
    ull d;
    asm("mov.b64 %0, {%1, %2};" : "=l"(d) : "r"(__float_as_uint(lo)), "r"(__float_as_uint(hi)));
    return d;
}
__device__ __forceinline__ float sum2(ull v) {
    unsigned lo, hi;
    asm("mov.b64 {%0, %1}, %2;" : "=r"(lo), "=r"(hi) : "l"(v));
    return __uint_as_float(lo) + __uint_as_float(hi);
}

// ---------------------------------------------------------------------------
// Launch 1: ELL build (one thread per edge, 2-way split counters, R13-proven)
// + spare threads pack W k-pairs into g_wp (coalesced reads of W rows).
__global__ void k_build(const int* __restrict__ psrc, const int* __restrict__ pdst,
                        const int* __restrict__ ssrc, const int* __restrict__ sdst,
                        int ep, int es, const float* __restrict__ W) {
    int i = blockIdx.x * blockDim.x + threadIdx.x;
    if (i < ep) {
        int d = pdst[i];
        int sub = i & 1;
        int slot = atomicAdd(&g_pcnt[d * 2 + sub], 1);
        if (slot < SEG) g_pesrc[d * STRIDE + sub * SEG + slot] = psrc[i];
        return;
    }
    int j = i - ep;
    if (j < es) {
        int d = sdst[j];
        int sub = j & 1;
        int slot = atomicAdd(&g_scnt[d * 2 + sub], 1);
        if (slot < SEG) g_sesrc[d * STRIDE + sub * SEG + slot] = ssrc[j];
        return;
    }
    int i2 = j - es;
    if (i2 < 64 * H) {                       // 8192 pack threads
        int c = i2 >> 6, kk2 = i2 & 63;
        float2 w2 = *reinterpret_cast<const float2*>(W + c * H + 2 * kk2);
        g_wp[kk2 * H + c] = packf2(w2.x, w2.y);
    }
}

// ---------------------------------------------------------------------------
// Warp-level ELL segment gather (proven 4-unroll shape). cnt <= 32.
__device__ __forceinline__ float4 gather_seg(const float* __restrict__ src,
                                             const int* __restrict__ row,
                                             int cnt, int lane, float4 acc) {
    int sidx = (lane < cnt) ? row[lane] : 0;
    int j = 0;
    for (; j + 4 <= cnt; j += 4) {
        int s0 = __shfl_sync(0xFFFFFFFFu, sidx, j);
        int s1 = __shfl_sync(0xFFFFFFFFu, sidx, j + 1);
        int s2 = __shfl_sync(0xFFFFFFFFu, sidx, j + 2);
        int s3 = __shfl_sync(0xFFFFFFFFu, sidx, j + 3);
        float4 a = __ldg(reinterpret_cast<const float4*>(src + (size_t)s0 * H) + lane);
        float4 b = __ldg(reinterpret_cast<const float4*>(src + (size_t)s1 * H) + lane);
        float4 c4 = __ldg(reinterpret_cast<const float4*>(src + (size_t)s2 * H) + lane);
        float4 f = __ldg(reinterpret_cast<const float4*>(src + (size_t)s3 * H) + lane);
        acc.x += (a.x + b.x) + (c4.x + f.x);
        acc.y += (a.y + b.y) + (c4.y + f.y);
        acc.z += (a.z + b.z) + (c4.z + f.z);
        acc.w += (a.w + b.w) + (c4.w + f.w);
    }
    for (; j < cnt; j++) {
        int s = __shfl_sync(0xFFFFFFFFu, sidx, j);
        float4 a = __ldg(reinterpret_cast<const float4*>(src + (size_t)s * H) + lane);
        acc.x += a.x; acc.y += a.y; acc.z += a.z; acc.w += a.w;
    }
    return acc;
}

// ---------------------------------------------------------------------------
// Launch 2: gathers, one warp per (row, edge set), two segments per row.
// Parent -> g_agg, sibling -> g_sagg. Resets cnt arrays for the next replay.
__global__ void k_gather(const float* __restrict__ prop_z,
                         const float* __restrict__ mol_z,
                         int n_prop) {
    int gw = (blockIdx.x * blockDim.x + threadIdx.x) >> 5;
    int lane = threadIdx.x & 31;
    bool sib = gw >= n_prop;
    int d = sib ? gw - n_prop : gw;
    if (d >= n_prop) return;
    int* cntp = sib ? g_scnt : g_pcnt;
    const int* row = (sib ? g_sesrc : g_pesrc) + (size_t)d * STRIDE;
    const float* src = sib ? mol_z : prop_z;

    int c0 = cntp[d * 2];
    int c1 = cntp[d * 2 + 1];
    if (c0 > SEG) c0 = SEG;
    if (c1 > SEG) c1 = SEG;

    float4 acc = make_float4(0.f, 0.f, 0.f, 0.f);
    acc = gather_seg(src, row, c0, lane, acc);
    acc = gather_seg(src, row + SEG, c1, lane, acc);

    if (lane == 0) { cntp[d * 2] = 0; cntp[d * 2 + 1] = 0; }   // replay reset

    float* dstb = sib ? g_sagg : g_agg;
    reinterpret_cast<float4*>(dstb + (size_t)d * H)[lane] = acc;
}

// ---------------------------------------------------------------------------
// Launch 3 (block-specialized, R13 structure):
//   blocks [0, G):  GEMM + combine, k-pair FFMA2 (no pack MOVs in inner loop).
//                   out[row] = prop_z[row] + g_sagg[row] + relu(acc + bias).
//   blocks [G, ..): copy rows [n_prop, n_nodes) of prop_z -> out (4 f4/thread).
__global__ void __launch_bounds__(256) k_gemm(const float* __restrict__ prop_z,
                                              const float* __restrict__ bias,
                                              float* __restrict__ out,
                                              int n_prop, int G,
                                              int off4, int n4copy) {
    int tid = threadIdx.x;
    if ((int)blockIdx.x >= G) {
        const float4* src = reinterpret_cast<const float4*>(prop_z);
        float4* dst = reinterpret_cast<float4*>(out);
        int base = (blockIdx.x - G) * 1024 + tid;
        int i0 = base, i1 = base + 256, i2 = base + 512, i3 = base + 768;
        float4 v0, v1, v2, v3;
        bool b0 = i0 < n4copy, b1 = i1 < n4copy, b2 = i2 < n4copy, b3 = i3 < n4copy;
        if (b0) v0 = src[off4 + i0];
        if (b1) v1 = src[off4 + i1];
        if (b2) v2 = src[off4 + i2];
        if (b3) v3 = src[off4 + i3];
        if (b0) dst[off4 + i0] = v0;
        if (b1) dst[off4 + i1] = v1;
        if (b2) dst[off4 + i2] = v2;
        if (b3) dst[off4 + i3] = v3;
        return;
    }

    __shared__ float As[32][132];       // [row][k]; float4 stores -> (k,k+1) adjacent
    __shared__ ull Wsp[8][H];           // [kk2][c] k-pair tile of W^T (8KB)
    int lane = tid & 31;
    int w = tid >> 5;
    int row0 = blockIdx.x * 32;

    // Load As from g_agg (coalesced float4), zero-pad rows beyond n_prop.
    {
        const float4 z4 = make_float4(0.f, 0.f, 0.f, 0.f);
        for (int i = tid; i < 32 * 32; i += 256) {
            int r = i >> 5, c4 = i & 31;
            int rr = row0 + r;
            float4 v = (rr < n_prop)
                ? *(reinterpret_cast<const float4*>(g_agg + (size_t)rr * H) + c4) : z4;
            *reinterpret_cast<float4*>(&As[r][c4 * 4]) = v;
        }
    }

    ull acc2[4][4];                     // [row][col], each holds (even-k, odd-k) partial
#pragma unroll
    for (int i = 0; i < 4; i++)
#pragma unroll
        for (int j = 0; j < 4; j++) acc2[i][j] = 0ull;

#pragma unroll 1
    for (int t = 0; t < 8; t++) {       // 8 tiles of 16 k (= 8 k-pairs)
        __syncthreads();
        for (int i = tid; i < 8 * H; i += 256)
            Wsp[i >> 7][i & 127] = g_wp[t * (8 * H) + i];
        __syncthreads();
#pragma unroll
        for (int kk2 = 0; kk2 < 8; kk2++) {
            const ull* wp = &Wsp[kk2][lane * 4];
            ull w0 = wp[0], w1 = wp[1], w2 = wp[2], w3 = wp[3];
#pragma unroll
            for (int i = 0; i < 4; i++) {
                ull a2 = *reinterpret_cast<const ull*>(&As[w * 4 + i][t * 16 + 2 * kk2]);
                acc2[i][0] = fma2(a2, w0, acc2[i][0]);
                acc2[i][1] = fma2(a2, w1, acc2[i][1]);
                acc2[i][2] = fma2(a2, w2, acc2[i][2]);
                acc2[i][3] = fma2(a2, w3, acc2[i][3]);
            }
        }
    }

    float4 b4 = __ldg(reinterpret_cast<const float4*>(bias) + lane);
#pragma unroll
    for (int i = 0; i < 4; i++) {
        int row = row0 + w * 4 + i;
        if (row < n_prop) {
            float4 pz = __ldg(reinterpret_cast<const float4*>(prop_z + (size_t)row * H) + lane);
            float4 sg = *(reinterpret_cast<const float4*>(g_sagg + (size_t)row * H) + lane);
            float4 v;
            v.x = pz.x + sg.x + fmaxf(sum2(acc2[i][0]) + b4.x, 0.f);
            v.y = pz.y + sg.y + fmaxf(sum2(acc2[i][1]) + b4.y, 0.f);
            v.z = pz.z + sg.z + fmaxf(sum2(acc2[i][2]) + b4.z, 0.f);
            v.w = pz.w + sg.w + fmaxf(sum2(acc2[i][3]) + b4.w, 0.f);
            reinterpret_cast<float4*>(out + (size_t)row * H)[lane] = v;
        }
    }
}

extern "C" void kernel_launch(void* const* d_in, const int* in_sizes, int n_in,
                              void* d_out, int out_size) {
    const float* prop_z = (const float*)d_in[0];
    const float* mol_z  = (const float*)d_in[1];
    const float* W      = (const float*)d_in[2];
    const float* b      = (const float*)d_in[3];
    const int* psrc = (const int*)d_in[4];
    const int* pdst = (const int*)d_in[5];
    const int* ssrc = (const int*)d_in[6];
    const int* sdst = (const int*)d_in[7];

    int n_nodes = in_sizes[0] / H;
    int ep      = in_sizes[4];
    int es      = in_sizes[6];
    int n_prop  = in_sizes[8];
    float* out  = (float*)d_out;

    int bt = ep + es + 64 * H;          // edges + W-pack threads
    k_build<<<(bt + 255) / 256, 256>>>(psrc, pdst, ssrc, sdst, ep, es, W);

    long long gt = (long long)2 * n_prop * 32;
    k_gather<<<(int)((gt + 255) / 256), 256>>>(prop_z, mol_z, n_prop);

    int off4 = n_prop * (H / 4);
    int n4copy = (n_nodes - n_prop) * (H / 4);
    int G = (n_prop + 31) / 32;
    int NC = (n4copy + 1023) / 1024;
    k_gemm<<<G + NC, 256>>>(prop_z, b, out, n_prop, G, off4, n4copy);
}

// round 16
// speedup vs baseline: 1.0510x; 1.0510x over previous
#include <cuda_runtime.h>

#define H 128
#define MAXP 25000
#define STRIDE 64        // total ELL row stride: 2 segments x 32 slots
#define SEG 32           // slots per segment (Poisson(12) per segment => safe)

typedef unsigned long long ull;

// Device-global scratch (allocations forbidden). Zero at load; cnt arrays are
// reset by k_gather after use so every graph replay starts clean.
__device__ __align__(256) float g_agg[MAXP * H];
__device__ __align__(256) float g_sagg[MAXP * H];
__device__ int g_pcnt[MAXP * 2], g_scnt[MAXP * 2];   // 2 sub-counters per row
__device__ int g_pesrc[MAXP * STRIDE], g_sesrc[MAXP * STRIDE];
__device__ __align__(16) ull g_wp[64 * H];  // g_wp[kk2*H + c] = (W[c][2kk2], W[c][2kk2+1])

__device__ __forceinline__ ull fma2(ull a, ull b, ull c) {
    ull d;
    asm("fma.rn.f32x2 %0, %1, %2, %3;" : "=l"(d) : "l"(a), "l"(b), "l"(c));
    return d;
}
__device__ __forceinline__ ull packf2(float lo, float hi) {
    ull d;
    asm("mov.b64 %0, {%1, %2};" : "=l"(d) : "r"(__float_as_uint(lo)), "r"(__float_as_uint(hi)));
    return d;
}
__device__ __forceinline__ float sum2(ull v) {
    unsigned lo, hi;
    asm("mov.b64 {%0, %1}, %2;" : "=r"(lo), "=r"(hi) : "l"(v));
    return __uint_as_float(lo) + __uint_as_float(hi);
}

// ---------------------------------------------------------------------------
// Launch 1: ELL build (one thread per edge, 2-way split counters, R13-proven)
// + spare threads pack W k-pairs into g_wp (free rider, measured in R15).
__global__ void k_build(const int* __restrict__ psrc, const int* __restrict__ pdst,
                        const int* __restrict__ ssrc, const int* __restrict__ sdst,
                        int ep, int es, const float* __restrict__ W) {
    int i = blockIdx.x * blockDim.x + threadIdx.x;
    if (i < ep) {
        int d = pdst[i];
        int sub = i & 1;
        int slot = atomicAdd(&g_pcnt[d * 2 + sub], 1);
        if (slot < SEG) g_pesrc[d * STRIDE + sub * SEG + slot] = psrc[i];
        return;
    }
    int j = i - ep;
    if (j < es) {
        int d = sdst[j];
        int sub = j & 1;
        int slot = atomicAdd(&g_scnt[d * 2 + sub], 1);
        if (slot < SEG) g_sesrc[d * STRIDE + sub * SEG + slot] = ssrc[j];
        return;
    }
    int i2 = j - es;
    if (i2 < 64 * H) {                       // 8192 pack threads
        int c = i2 >> 6, kk2 = i2 & 63;
        float2 w2 = *reinterpret_cast<const float2*>(W + c * H + 2 * kk2);
        g_wp[kk2 * H + c] = packf2(w2.x, w2.y);
    }
}

// ---------------------------------------------------------------------------
// Warp-level ELL segment gather (proven 4-unroll shape). cnt <= 32.
__device__ __forceinline__ float4 gather_seg(const float* __restrict__ src,
                                             const int* __restrict__ row,
                                             int cnt, int lane, float4 acc) {
    int sidx = (lane < cnt) ? row[lane] : 0;
    int j = 0;
    for (; j + 4 <= cnt; j += 4) {
        int s0 = __shfl_sync(0xFFFFFFFFu, sidx, j);
        int s1 = __shfl_sync(0xFFFFFFFFu, sidx, j + 1);
        int s2 = __shfl_sync(0xFFFFFFFFu, sidx, j + 2);
        int s3 = __shfl_sync(0xFFFFFFFFu, sidx, j + 3);
        float4 a = __ldg(reinterpret_cast<const float4*>(src + (size_t)s0 * H) + lane);
        float4 b = __ldg(reinterpret_cast<const float4*>(src + (size_t)s1 * H) + lane);
        float4 c4 = __ldg(reinterpret_cast<const float4*>(src + (size_t)s2 * H) + lane);
        float4 f = __ldg(reinterpret_cast<const float4*>(src + (size_t)s3 * H) + lane);
        acc.x += (a.x + b.x) + (c4.x + f.x);
        acc.y += (a.y + b.y) + (c4.y + f.y);
        acc.z += (a.z + b.z) + (c4.z + f.z);
        acc.w += (a.w + b.w) + (c4.w + f.w);
    }
    for (; j < cnt; j++) {
        int s = __shfl_sync(0xFFFFFFFFu, sidx, j);
        float4 a = __ldg(reinterpret_cast<const float4*>(src + (size_t)s * H) + lane);
        acc.x += a.x; acc.y += a.y; acc.z += a.z; acc.w += a.w;
    }
    return acc;
}

// ---------------------------------------------------------------------------
// Launch 2: gathers, one warp per (row, edge set), two segments per row.
// Parent -> g_agg, sibling -> g_sagg. Resets cnt arrays for the next replay.
__global__ void k_gather(const float* __restrict__ prop_z,
                         const float* __restrict__ mol_z,
                         int n_prop) {
    int gw = (blockIdx.x * blockDim.x + threadIdx.x) >> 5;
    int lane = threadIdx.x & 31;
    bool sib = gw >= n_prop;
    int d = sib ? gw - n_prop : gw;
    if (d >= n_prop) return;
    int* cntp = sib ? g_scnt : g_pcnt;
    const int* row = (sib ? g_sesrc : g_pesrc) + (size_t)d * STRIDE;
    const float* src = sib ? mol_z : prop_z;

    int c0 = cntp[d * 2];
    int c1 = cntp[d * 2 + 1];
    if (c0 > SEG) c0 = SEG;
    if (c1 > SEG) c1 = SEG;

    float4 acc = make_float4(0.f, 0.f, 0.f, 0.f);
    acc = gather_seg(src, row, c0, lane, acc);
    acc = gather_seg(src, row + SEG, c1, lane, acc);

    if (lane == 0) { cntp[d * 2] = 0; cntp[d * 2 + 1] = 0; }   // replay reset

    float* dstb = sib ? g_sagg : g_agg;
    reinterpret_cast<float4*>(dstb + (size_t)d * H)[lane] = acc;
}

// ---------------------------------------------------------------------------
// Launch 3 (block-specialized, R13 structure):
//   blocks [0, G):  GEMM + combine, k-pair FFMA2 with CONFLICT-FREE W layout:
//                   thread owns columns {lane, lane+32, lane+64, lane+96}
//                   (LDS.64 lane stride 8B -> no bank conflicts).
//                   out[row] = prop_z[row] + g_sagg[row] + relu(acc + bias).
//   blocks [G, ..): copy rows [n_prop, n_nodes) of prop_z -> out (4 f4/thread).
__global__ void __launch_bounds__(256) k_gemm(const float* __restrict__ prop_z,
                                              const float* __restrict__ bias,
                                              float* __restrict__ out,
                                              int n_prop, int G,
                                              int off4, int n4copy) {
    int tid = threadIdx.x;
    if ((int)blockIdx.x >= G) {
        const float4* src = reinterpret_cast<const float4*>(prop_z);
        float4* dst = reinterpret_cast<float4*>(out);
        int base = (blockIdx.x - G) * 1024 + tid;
        int i0 = base, i1 = base + 256, i2 = base + 512, i3 = base + 768;
        float4 v0, v1, v2, v3;
        bool b0 = i0 < n4copy, b1 = i1 < n4copy, b2 = i2 < n4copy, b3 = i3 < n4copy;
        if (b0) v0 = src[off4 + i0];
        if (b1) v1 = src[off4 + i1];
        if (b2) v2 = src[off4 + i2];
        if (b3) v3 = src[off4 + i3];
        if (b0) dst[off4 + i0] = v0;
        if (b1) dst[off4 + i1] = v1;
        if (b2) dst[off4 + i2] = v2;
        if (b3) dst[off4 + i3] = v3;
        return;
    }

    __shared__ float As[32][132];       // [row][k]; row stride 528B (8B aligned)
    __shared__ ull Wsp[8][H];           // [kk2][c] k-pair tile of W^T (8KB)
    int lane = tid & 31;
    int w = tid >> 5;
    int row0 = blockIdx.x * 32;

    // Load As from g_agg (coalesced float4), zero-pad rows beyond n_prop.
    {
        const float4 z4 = make_float4(0.f, 0.f, 0.f, 0.f);
        for (int i = tid; i < 32 * 32; i += 256) {
            int r = i >> 5, c4 = i & 31;
            int rr = row0 + r;
            float4 v = (rr < n_prop)
                ? *(reinterpret_cast<const float4*>(g_agg + (size_t)rr * H) + c4) : z4;
            *reinterpret_cast<float4*>(&As[r][c4 * 4]) = v;
        }
    }

    ull acc2[4][4];                     // [row][q]; cols lane+32q; (even,odd) k partials
#pragma unroll
    for (int i = 0; i < 4; i++)
#pragma unroll
        for (int q = 0; q < 4; q++) acc2[i][q] = 0ull;

#pragma unroll 1
    for (int t = 0; t < 8; t++) {       // 8 tiles of 16 k (= 8 k-pairs)
        __syncthreads();
        for (int i = tid; i < 8 * H; i += 256)
            Wsp[i >> 7][i & 127] = g_wp[t * (8 * H) + i];
        __syncthreads();
#pragma unroll
        for (int kk2 = 0; kk2 < 8; kk2++) {
            ull w0 = Wsp[kk2][lane];
            ull w1 = Wsp[kk2][lane + 32];
            ull w2 = Wsp[kk2][lane + 64];
            ull w3 = Wsp[kk2][lane + 96];
#pragma unroll
            for (int i = 0; i < 4; i++) {
                ull a2 = *reinterpret_cast<const ull*>(&As[w * 4 + i][t * 16 + 2 * kk2]);
                acc2[i][0] = fma2(a2, w0, acc2[i][0]);
                acc2[i][1] = fma2(a2, w1, acc2[i][1]);
                acc2[i][2] = fma2(a2, w2, acc2[i][2]);
                acc2[i][3] = fma2(a2, w3, acc2[i][3]);
            }
        }
    }

    float bb[4];
#pragma unroll
    for (int q = 0; q < 4; q++) bb[q] = __ldg(bias + lane + 32 * q);

#pragma unroll
    for (int i = 0; i < 4; i++) {
        int row = row0 + w * 4 + i;
        if (row < n_prop) {
            const float* pz = prop_z + (size_t)row * H;
            const float* sg = g_sagg + (size_t)row * H;
            float* o = out + (size_t)row * H;
#pragma unroll
            for (int q = 0; q < 4; q++) {
                int c = lane + 32 * q;
                o[c] = __ldg(pz + c) + sg[c] + fmaxf(sum2(acc2[i][q]) + bb[q], 0.f);
            }
        }
    }
}

extern "C" void kernel_launch(void* const* d_in, const int* in_sizes, int n_in,
                              void* d_out, int out_size) {
    const float* prop_z = (const float*)d_in[0];
    const float* mol_z  = (const float*)d_in[1];
    const float* W      = (const float*)d_in[2];
    const float* b      = (const float*)d_in[3];
    const int* psrc = (const int*)d_in[4];
    const int* pdst = (const int*)d_in[5];
    const int* ssrc = (const int*)d_in[6];
    const int* sdst = (const int*)d_in[7];

    int n_nodes = in_sizes[0] / H;
    int ep      = in_sizes[4];
    int es      = in_sizes[6];
    int n_prop  = in_sizes[8];
    float* out  = (float*)d_out;

    int bt = ep + es + 64 * H;          // edges + W-pack threads
    k_build<<<(bt + 255) / 256, 256>>>(psrc, pdst, ssrc, sdst, ep, es, W);

    long long gt = (long long)2 * n_prop * 32;
    k_gather<<<(int)((gt + 255) / 256), 256>>>(prop_z, mol_z, n_prop);

    int off4 = n_prop * (H / 4);
    int n4copy = (n_nodes - n_prop) * (H / 4);
    int G = (n_prop + 31) / 32;
    int NC = (n4copy + 1023) / 1024;
    k_gemm<<<G + NC, 256>>>(prop_z, b, out, n_prop, G, off4, n4copy);
}

// round 17
// speedup vs baseline: 1.2166x; 1.1575x over previous
#include <cuda_runtime.h>

#define H 128
#define MAXP 25000
#define STRIDE 64        // total ELL row stride: 2 segments x 32 slots
#define SEG 32           // slots per segment (Poisson(12) per segment => safe)

typedef unsigned long long ull;

// Device-global scratch (allocations forbidden). Zero at load; cnt arrays are
// reset by k_gather after use so every graph replay starts clean.
__device__ __align__(256) float g_agg[MAXP * H];
__device__ __align__(256) float g_sagg[MAXP * H];
__device__ int g_pcnt[MAXP * 2], g_scnt[MAXP * 2];   // 2 sub-counters per row
__device__ int g_pesrc[MAXP * STRIDE], g_sesrc[MAXP * STRIDE];

__device__ __forceinline__ ull fma2(ull a, ull b, ull c) {
    ull d;
    asm("fma.rn.f32x2 %0, %1, %2, %3;" : "=l"(d) : "l"(a), "l"(b), "l"(c));
    return d;
}
__device__ __forceinline__ ull pack2(float x) {
    ull d;
    unsigned u = __float_as_uint(x);
    asm("mov.b64 %0, {%1, %2};" : "=l"(d) : "r"(u), "r"(u));
    return d;
}
__device__ __forceinline__ float2 unpack2(ull v) {
    unsigned lo, hi;
    asm("mov.b64 {%0, %1}, %2;" : "=r"(lo), "=r"(hi) : "l"(v));
    return make_float2(__uint_as_float(lo), __uint_as_float(hi));
}

// ---------------------------------------------------------------------------
// Launch 1: ELL build, one thread per edge, 2-way split counters:
// sub = e & 1 halves atomic ops per address (the measured build bottleneck).
__global__ void k_build(const int* __restrict__ psrc, const int* __restrict__ pdst,
                        const int* __restrict__ ssrc, const int* __restrict__ sdst,
                        int ep, int es) {
    int i = blockIdx.x * blockDim.x + threadIdx.x;
    if (i < ep) {
        int d = pdst[i];
        int sub = i & 1;
        int slot = atomicAdd(&g_pcnt[d * 2 + sub], 1);
        if (slot < SEG) g_pesrc[d * STRIDE + sub * SEG + slot] = psrc[i];
    } else {
        int j = i - ep;
        if (j < es) {
            int d = sdst[j];
            int sub = j & 1;
            int slot = atomicAdd(&g_scnt[d * 2 + sub], 1);
            if (slot < SEG) g_sesrc[d * STRIDE + sub * SEG + slot] = ssrc[j];
        }
    }
}

// ---------------------------------------------------------------------------
// Warp-level ELL segment gather (proven 4-unroll shape). cnt <= 32.
__device__ __forceinline__ float4 gather_seg(const float* __restrict__ src,
                                             const int* __restrict__ row,
                                             int cnt, int lane, float4 acc) {
    int sidx = (lane < cnt) ? row[lane] : 0;
    int j = 0;
    for (; j + 4 <= cnt; j += 4) {
        int s0 = __shfl_sync(0xFFFFFFFFu, sidx, j);
        int s1 = __shfl_sync(0xFFFFFFFFu, sidx, j + 1);
        int s2 = __shfl_sync(0xFFFFFFFFu, sidx, j + 2);
        int s3 = __shfl_sync(0xFFFFFFFFu, sidx, j + 3);
        float4 a = __ldg(reinterpret_cast<const float4*>(src + (size_t)s0 * H) + lane);
        float4 b = __ldg(reinterpret_cast<const float4*>(src + (size_t)s1 * H) + lane);
        float4 c4 = __ldg(reinterpret_cast<const float4*>(src + (size_t)s2 * H) + lane);
        float4 f = __ldg(reinterpret_cast<const float4*>(src + (size_t)s3 * H) + lane);
        acc.x += (a.x + b.x) + (c4.x + f.x);
        acc.y += (a.y + b.y) + (c4.y + f.y);
        acc.z += (a.z + b.z) + (c4.z + f.z);
        acc.w += (a.w + b.w) + (c4.w + f.w);
    }
    for (; j < cnt; j++) {
        int s = __shfl_sync(0xFFFFFFFFu, sidx, j);
        float4 a = __ldg(reinterpret_cast<const float4*>(src + (size_t)s * H) + lane);
        acc.x += a.x; acc.y += a.y; acc.z += a.z; acc.w += a.w;
    }
    return acc;
}

// ---------------------------------------------------------------------------
// Launch 2: gathers, one warp per (row, edge set), two segments per row.
// Parent -> g_agg, sibling -> g_sagg. Resets cnt arrays for the next replay.
__global__ void k_gather(const float* __restrict__ prop_z,
                         const float* __restrict__ mol_z,
                         int n_prop) {
    int gw = (blockIdx.x * blockDim.x + threadIdx.x) >> 5;
    int lane = threadIdx.x & 31;
    bool sib = gw >= n_prop;
    int d = sib ? gw - n_prop : gw;
    if (d >= n_prop) return;
    int* cntp = sib ? g_scnt : g_pcnt;
    const int* row = (sib ? g_sesrc : g_pesrc) + (size_t)d * STRIDE;
    const float* src = sib ? mol_z : prop_z;

    int c0 = cntp[d * 2];
    int c1 = cntp[d * 2 + 1];
    if (c0 > SEG) c0 = SEG;
    if (c1 > SEG) c1 = SEG;

    float4 acc = make_float4(0.f, 0.f, 0.f, 0.f);
    acc = gather_seg(src, row, c0, lane, acc);
    acc = gather_seg(src, row + SEG, c1, lane, acc);

    if (lane == 0) { cntp[d * 2] = 0; cntp[d * 2 + 1] = 0; }   // replay reset

    float* dstb = sib ? g_sagg : g_agg;
    reinterpret_cast<float4*>(dstb + (size_t)d * H)[lane] = acc;
}

// ---------------------------------------------------------------------------
// Launch 3 (block-specialized):
//   blocks [0, G):  GEMM + combine (32 rows, 256 thr, FFMA2).
//                   out[row] = prop_z[row] + g_sagg[row] + relu(acc + bias).
//   blocks [G, ..): copy rows [n_prop, n_nodes) of prop_z -> out (4 f4/thread).
__global__ void __launch_bounds__(256) k_gemm(const float* __restrict__ prop_z,
                                              const float* __restrict__ W,
                                              const float* __restrict__ bias,
                                              float* __restrict__ out,
                                              int n_prop, int G,
                                              int off4, int n4copy) {
    int tid = threadIdx.x;
    if ((int)blockIdx.x >= G) {
        const float4* src = reinterpret_cast<const float4*>(prop_z);
        float4* dst = reinterpret_cast<float4*>(out);
        int base = (blockIdx.x - G) * 1024 + tid;
        int i0 = base, i1 = base + 256, i2 = base + 512, i3 = base + 768;
        float4 v0, v1, v2, v3;
        bool b0 = i0 < n4copy, b1 = i1 < n4copy, b2 = i2 < n4copy, b3 = i3 < n4copy;
        if (b0) v0 = src[off4 + i0];
        if (b1) v1 = src[off4 + i1];
        if (b2) v2 = src[off4 + i2];
        if (b3) v3 = src[off4 + i3];
        if (b0) dst[off4 + i0] = v0;
        if (b1) dst[off4 + i1] = v1;
        if (b2) dst[off4 + i2] = v2;
        if (b3) dst[off4 + i3] = v3;
        return;
    }

    __shared__ float As[32][132];       // [row][k]
    __shared__ float Ws[16][132];       // [k][col] tile of W^T
    int lane = tid & 31;
    int w = tid >> 5;
    int row0 = blockIdx.x * 32;

    {
        const float4 z4 = make_float4(0.f, 0.f, 0.f, 0.f);
        for (int i = tid; i < 32 * 32; i += 256) {
            int r = i >> 5, c4 = i & 31;
            int rr = row0 + r;
            float4 v = (rr < n_prop)
                ? *(reinterpret_cast<const float4*>(g_agg + (size_t)rr * H) + c4) : z4;
            *reinterpret_cast<float4*>(&As[r][c4 * 4]) = v;
        }
    }

    ull acc2[4][2];
#pragma unroll
    for (int i = 0; i < 4; i++) { acc2[i][0] = pack2(0.f); acc2[i][1] = pack2(0.f); }

#pragma unroll 1
    for (int kt = 0; kt < H; kt += 16) {
        __syncthreads();
        for (int i = tid; i < 16 * H; i += 256) {
            int kk = i & 15, c = i >> 4;
            Ws[kk][c] = W[c * H + kt + kk];
        }
        __syncthreads();
#pragma unroll
        for (int kk = 0; kk < 16; kk++) {
            const ull* wp = reinterpret_cast<const ull*>(&Ws[kk][lane * 4]);
            ull w01 = wp[0], w23 = wp[1];
#pragma unroll
            for (int i = 0; i < 4; i++) {
                ull a2 = pack2(As[w * 4 + i][kt + kk]);   // warp broadcast
                acc2[i][0] = fma2(a2, w01, acc2[i][0]);
                acc2[i][1] = fma2(a2, w23, acc2[i][1]);
            }
        }
    }

    float4 b4 = __ldg(reinterpret_cast<const float4*>(bias) + lane);
#pragma unroll
    for (int i = 0; i < 4; i++) {
        int row = row0 + w * 4 + i;
        if (row < n_prop) {
            float2 p0 = unpack2(acc2[i][0]);
            float2 p1 = unpack2(acc2[i][1]);
            float4 pz = __ldg(reinterpret_cast<const float4*>(prop_z + (size_t)row * H) + lane);
            float4 sg = *(reinterpret_cast<const float4*>(g_sagg + (size_t)row * H) + lane);
            float4 v;
            v.x = pz.x + sg.x + fmaxf(p0.x + b4.x, 0.f);
            v.y = pz.y + sg.y + fmaxf(p0.y + b4.y, 0.f);
            v.z = pz.z + sg.z + fmaxf(p1.x + b4.z, 0.f);
            v.w = pz.w + sg.w + fmaxf(p1.y + b4.w, 0.f);
            reinterpret_cast<float4*>(out + (size_t)row * H)[lane] = v;
        }
    }
}

extern "C" void kernel_launch(void* const* d_in, const int* in_sizes, int n_in,
                              void* d_out, int out_size) {
    const float* prop_z = (const float*)d_in[0];
    const float* mol_z  = (const float*)d_in[1];
    const float* W      = (const float*)d_in[2];
    const float* b      = (const float*)d_in[3];
    const int* psrc = (const int*)d_in[4];
    const int* pdst = (const int*)d_in[5];
    const int* ssrc = (const int*)d_in[6];
    const int* sdst = (const int*)d_in[7];

    int n_nodes = in_sizes[0] / H;
    int ep      = in_sizes[4];
    int es      = in_sizes[6];
    int n_prop  = in_sizes[8];
    float* out  = (float*)d_out;

    int ne = ep + es;
    k_build<<<(ne + 255) / 256, 256>>>(psrc, pdst, ssrc, sdst, ep, es);

    long long gt = (long long)2 * n_prop * 32;
    k_gather<<<(int)((gt + 255) / 256), 256>>>(prop_z, mol_z, n_prop);

    int off4 = n_prop * (H / 4);
    int n4copy = (n_nodes - n_prop) * (H / 4);
    int G = (n_prop + 31) / 32;
    int NC = (n4copy + 1023) / 1024;
    k_gemm<<<G + NC, 256>>>(prop_z, W, b, out, n_prop, G, off4, n4copy);
}